// round 13
// baseline (speedup 1.0000x reference)
#include <cuda_runtime.h>
#include <cuda_bf16.h>
#include <math.h>
#include <stdint.h>

#define NQ       2048
#define ND       100000
#define DIM      16
#define QTILES   16            // 2048 / 128 queries per CTA
#define DS       37            // data splits; 16*37 = 592 CTAs = 4/SM (1 wave)
#define NCTA     (QTILES * DS) // 592
#define TILE     256           // data points per smem tile
#define NT       11            // tiles per split
#define PTS_PER_SPLIT (TILE * NT)            // 2816
#define PPC      (PTS_PER_SPLIT / QTILES)    // 176 points converted per CTA
#define NPAD     (DS * PTS_PER_SPLIT)        // 104192
#define THREADS  256
#define PROW     80            // padded partials row (74 used)

// ---- device scratch (no allocations allowed) ----
// g_dcat: per point, 16 tf32 words, PERMUTED: pos 4g+{0..3} = natural words
//         {g, g+4, g+8, g+12}. One LDS.128 per lane yields both k8 B
//         fragments for m16n8k8 tf32.
__device__ float4 g_dcat[(size_t)NPAD * 4];
__device__ float g_coeff[NPAD];             // w_j * exp(-0.5*||d||^2)
__device__ float g_partials[(size_t)NQ * PROW];
__device__ float g_wpart[NCTA];             // per-CTA w partial sums
__device__ unsigned g_arrive[DS];           // per-split arrival counters
__device__ unsigned g_depart;               // wrap counter (self-resetting)

// ---- helpers ----
__device__ __forceinline__ uint32_t s2u(const void* p) {
    uint32_t a;
    asm("{ .reg .u64 t; cvta.to.shared.u64 t, %1; cvt.u32.u64 %0, t; }"
        : "=r"(a) : "l"(p));
    return a;
}
__device__ __forceinline__ void cpa16(uint32_t dst, const void* src) {
    asm volatile("cp.async.cg.shared.global [%0], [%1], 16;"
                 :: "r"(dst), "l"(src));
}
#define CP_COMMIT() asm volatile("cp.async.commit_group;" ::: "memory")
#define CP_WAIT0()  asm volatile("cp.async.wait_group 0;" ::: "memory")
#define CP_WAIT1()  asm volatile("cp.async.wait_group 1;" ::: "memory")

__device__ __forceinline__ float ex2f(float x) {
    float r; asm("ex2.approx.f32 %0, %1;" : "=f"(r) : "f"(x)); return r;
}
__device__ __forceinline__ float tf32r(float x) {
    float r; asm("cvt.rna.tf32.f32 %0, %1;" : "=f"(r) : "f"(x)); return r;
}
__device__ __forceinline__ void mma_tf32(float* d, const uint32_t* a,
                                         uint32_t b0, uint32_t b1) {
    asm volatile(
        "mma.sync.aligned.m16n8k8.row.col.f32.tf32.tf32.f32 "
        "{%0,%1,%2,%3}, {%4,%5,%6,%7}, {%8,%9}, {%0,%1,%2,%3};"
        : "+f"(d[0]), "+f"(d[1]), "+f"(d[2]), "+f"(d[3])
        : "r"(a[0]), "r"(a[1]), "r"(a[2]), "r"(a[3]), "r"(b0), "r"(b1));
}
__device__ __forceinline__ void lds128(uint32_t addr, uint32_t* v) {
    asm volatile("ld.shared.v4.u32 {%0,%1,%2,%3}, [%4];"
                 : "=r"(v[0]), "=r"(v[1]), "=r"(v[2]), "=r"(v[3]) : "r"(addr));
}

// ---------------------------------------------------------------------------
// Main (single compute kernel):
//   Phase 0: CTA (qt,ds) converts ITS OWN split's slice of 176 raw points ->
//            tf32 permuted g_dcat + g_coeff (+ per-CTA w sum). Per-split
//            16-arrival spin barrier (safe: grid = exactly 1 resident wave,
//            guaranteed by __launch_bounds__(256,4) and 592 = 148*4).
//   Phase 1: R7-proven loop: 128 queries x 2816 points, tf32 m16n8k8,
//            MUFU ex2 epilogue, double-buffered cp.async tiles.
// ---------------------------------------------------------------------------
__global__ __launch_bounds__(THREADS, 4)
void kde_main_kernel(const float* __restrict__ X,
                     const float* __restrict__ data,
                     const float* __restrict__ wvec) {
    __shared__ uint4 sd[2][TILE * 4];   // 2 x 16 KB, 64B per point (permuted)
    __shared__ float sc[2][TILE];
    __shared__ float redw[THREADS];

    int tid = threadIdx.x;
    int w = tid >> 5, lane = tid & 31;
    int wm = w >> 1, wn = w & 1;
    int qt = blockIdx.x, ds = blockIdx.y;
    int cta = ds * QTILES + qt;
    int p0base = ds * PTS_PER_SPLIT;
    int r = lane >> 2, cg = lane & 3, c2 = cg * 2;

    const float LOG2E = 1.4426950408889634f;

    // ---- Phase 0: convert this CTA's 176-point slice ----
    {
        float wj = 0.0f;
        if (tid < PPC) {
            int j = p0base + qt * PPC + tid;
            float wd[16];
            float cj = 0.0f;
            if (j < ND) {
                const float4* src = (const float4*)(data + (size_t)j * DIM);
                float dn = 0.0f;
#pragma unroll
                for (int v = 0; v < 4; v++) {
                    float4 p = src[v];
                    dn += p.x * p.x + p.y * p.y + p.z * p.z + p.w * p.w;
                    wd[v * 4 + 0] = tf32r(p.x);
                    wd[v * 4 + 1] = tf32r(p.y);
                    wd[v * 4 + 2] = tf32r(p.z);
                    wd[v * 4 + 3] = tf32r(p.w);
                }
                wj = wvec[j];
                cj = wj * ex2f(-0.72134752044448170f * dn);  // = w*exp(-dn/2)
            } else {
#pragma unroll
                for (int k = 0; k < 16; k++) wd[k] = 0.0f;
            }
            g_coeff[j] = cj;
#pragma unroll
            for (int g = 0; g < 4; g++) {
                float4 o;
                o.x = wd[g]; o.y = wd[g + 4]; o.z = wd[g + 8]; o.w = wd[g + 12];
                g_dcat[(size_t)j * 4 + g] = o;
            }
        }
        redw[tid] = wj;
        __syncthreads();
#pragma unroll
        for (int s = THREADS / 2; s > 0; s >>= 1) {
            if (tid < s) redw[tid] += redw[tid + s];
            __syncthreads();
        }
        if (tid == 0) {
            g_wpart[cta] = redw[0];
            __threadfence();
            atomicAdd(&g_arrive[ds], 1u);
            while (atomicAdd(&g_arrive[ds], 0u) < (unsigned)QTILES) {}
            __threadfence();
        }
        __syncthreads();   // split ds fully converted & visible
    }

    // ---- A fragments straight from X ----
    int qb = qt * 128 + wm * 32;
    uint32_t afrag[2][2][4];
#pragma unroll
    for (int mt = 0; mt < 2; mt++)
#pragma unroll
        for (int kc = 0; kc < 2; kc++) {
            int q0 = qb + mt * 16 + r;
            int k0 = kc * 8 + cg;
            afrag[mt][kc][0] = __float_as_uint(tf32r(X[(size_t)q0 * 16 + k0] * LOG2E));
            afrag[mt][kc][1] = __float_as_uint(tf32r(X[(size_t)(q0 + 8) * 16 + k0] * LOG2E));
            afrag[mt][kc][2] = __float_as_uint(tf32r(X[(size_t)q0 * 16 + k0 + 4] * LOG2E));
            afrag[mt][kc][3] = __float_as_uint(tf32r(X[(size_t)(q0 + 8) * 16 + k0 + 4] * LOG2E));
        }

    // Stage tile 0
    {
        const char* bsrc = (const char*)(g_dcat + (size_t)p0base * 4);
        uint32_t sbb = s2u(sd[0]);
#pragma unroll
        for (int i = tid; i < TILE * 4; i += THREADS)
            cpa16(sbb + i * 16, bsrc + i * 16);
        if (tid < 64)
            cpa16(s2u(sc[0]) + tid * 16, (const char*)(g_coeff + p0base) + tid * 16);
        CP_COMMIT();
    }

    float acc[2][2] = {{0.0f, 0.0f}, {0.0f, 0.0f}};
    int buf = 0;

    for (int it = 0; it < NT; ++it) {
        if (it + 1 < NT) {
            int p0 = p0base + (it + 1) * TILE;
            const char* bsrc = (const char*)(g_dcat + (size_t)p0 * 4);
            uint32_t sbb = s2u(sd[buf ^ 1]);
#pragma unroll
            for (int i = tid; i < TILE * 4; i += THREADS)
                cpa16(sbb + i * 16, bsrc + i * 16);
            if (tid < 64)
                cpa16(s2u(sc[buf ^ 1]) + tid * 16, (const char*)(g_coeff + p0) + tid * 16);
            CP_COMMIT();
            CP_WAIT1();   // tile `it` resident
        } else {
            CP_WAIT0();
        }
        __syncthreads();

        uint32_t sdb = s2u(sd[buf]);
        const float* scf = sc[buf];
#pragma unroll
        for (int nt = 0; nt < 16; nt++) {
            int n0 = wn * 128 + nt * 8;
            uint32_t b[4];
            lds128(sdb + (uint32_t)(n0 + r) * 64 + (uint32_t)cg * 16, b);
            float d0[4] = {0, 0, 0, 0}, d1[4] = {0, 0, 0, 0};
            mma_tf32(d0, afrag[0][0], b[0], b[1]);
            mma_tf32(d1, afrag[1][0], b[0], b[1]);
            mma_tf32(d0, afrag[0][1], b[2], b[3]);
            mma_tf32(d1, afrag[1][1], b[2], b[3]);

            float2 cj = *(const float2*)(scf + n0 + c2);
            acc[0][0] = fmaf(cj.x, ex2f(d0[0]), acc[0][0]);
            acc[0][0] = fmaf(cj.y, ex2f(d0[1]), acc[0][0]);
            acc[0][1] = fmaf(cj.x, ex2f(d0[2]), acc[0][1]);
            acc[0][1] = fmaf(cj.y, ex2f(d0[3]), acc[0][1]);
            acc[1][0] = fmaf(cj.x, ex2f(d1[0]), acc[1][0]);
            acc[1][0] = fmaf(cj.y, ex2f(d1[1]), acc[1][0]);
            acc[1][1] = fmaf(cj.x, ex2f(d1[2]), acc[1][1]);
            acc[1][1] = fmaf(cj.y, ex2f(d1[3]), acc[1][1]);
        }
        __syncthreads();  // done reading buf before restage
        buf ^= 1;
    }

    // Reduce over the 4 column-lanes (fixed order, deterministic)
#pragma unroll
    for (int mt = 0; mt < 2; mt++)
#pragma unroll
        for (int hh = 0; hh < 2; hh++) {
            float v = acc[mt][hh];
            v += __shfl_xor_sync(0xFFFFFFFFu, v, 1);
            v += __shfl_xor_sync(0xFFFFFFFFu, v, 2);
            acc[mt][hh] = v;
        }
    if (cg == 0) {
        int col = ds * 2 + wn;
        g_partials[(size_t)(qb + r) * PROW + col]          = acc[0][0];
        g_partials[(size_t)(qb + r + 8) * PROW + col]      = acc[0][1];
        g_partials[(size_t)(qb + 16 + r) * PROW + col]     = acc[1][0];
        g_partials[(size_t)(qb + 16 + r + 8) * PROW + col] = acc[1][1];
    }

    // ---- depart: last CTA resets arrival counters (graph-replay safety) ----
    __syncthreads();
    if (tid == 0) {
        unsigned old = atomicInc(&g_depart, NCTA - 1);  // wraps to 0 on last
        if (old == NCTA - 1) {
#pragma unroll
            for (int s = 0; s < DS; s++) g_arrive[s] = 0u;
            __threadfence();
        }
    }
}

// ---------------------------------------------------------------------------
// Finalize: warp per query (PDL: ||x||^2 before grid sync). Block-level
// reduce of the 592 per-CTA w sums -> logsumw (fixed order, deterministic).
//   log_density = log(S) - 0.5||x||^2 - 8*log(2*pi) - logsumw
// ---------------------------------------------------------------------------
__global__ __launch_bounds__(256)
void kde_final_kernel(const float* __restrict__ X,
                      float* __restrict__ out) {
    __shared__ float red[256];
    __shared__ float s_logsumw;
    int t = threadIdx.x;
    int w = t >> 5, lane = t & 31;
    int q = blockIdx.x * 8 + w;

    // prep-independent prolog
    float qn = 0.0f;
    {
        const float4* row = (const float4*)(X + (size_t)q * DIM);
#pragma unroll
        for (int v = 0; v < 4; v++) {
            float4 p = row[v];
            qn += p.x * p.x + p.y * p.y + p.z * p.z + p.w * p.w;
        }
    }

    cudaGridDependencySynchronize();

    // logsumw: 592 slots, fixed order
    {
        float s = g_wpart[t] + g_wpart[t + 256];
        if (t + 512 < NCTA) s += g_wpart[t + 512];
        red[t] = s;
    }
    __syncthreads();
#pragma unroll
    for (int st = 128; st > 0; st >>= 1) {
        if (t < st) red[t] += red[t + st];
        __syncthreads();
    }
    if (t == 0) s_logsumw = logf(red[0]);
    __syncthreads();

    const float* pr = g_partials + (size_t)q * PROW;
    float S = pr[lane] + pr[lane + 32];
    if (lane < DS * 2 - 64) S += pr[lane + 64];
    // fixed-order shfl reduction
    S += __shfl_xor_sync(0xFFFFFFFFu, S, 16);
    S += __shfl_xor_sync(0xFFFFFFFFu, S, 8);
    S += __shfl_xor_sync(0xFFFFFFFFu, S, 4);
    S += __shfl_xor_sync(0xFFFFFFFFu, S, 2);
    S += __shfl_xor_sync(0xFFFFFFFFu, S, 1);

    if (lane == 0) {
        const float LOG2PI = 1.8378770664093453f;
        out[q] = logf(S) - 0.5f * qn - 8.0f * LOG2PI - s_logsumw;
    }
}

// ---------------------------------------------------------------------------
extern "C" void kernel_launch(void* const* d_in, const int* in_sizes, int n_in,
                              void* d_out, int out_size) {
    const float* X    = (const float*)d_in[0];  // [2048, 16]
    const float* data = (const float*)d_in[1];  // [100000, 16]
    const float* w    = (const float*)d_in[2];  // [100000]
    float* out = (float*)d_out;                 // [2048]

    kde_main_kernel<<<dim3(QTILES, DS), THREADS>>>(X, data, w);

    cudaLaunchAttribute attr[1];
    attr[0].id = cudaLaunchAttributeProgrammaticStreamSerialization;
    attr[0].val.programmaticStreamSerializationAllowed = 1;

    cudaLaunchConfig_t cfg = {};
    cfg.gridDim = dim3(NQ / 8);
    cfg.blockDim = dim3(256);
    cfg.dynamicSmemBytes = 0;
    cfg.attrs = attr;
    cfg.numAttrs = 1;
    cudaLaunchKernelEx(&cfg, kde_final_kernel, X, out);
}